// round 7
// baseline (speedup 1.0000x reference)
#include <cuda_runtime.h>
#include <cuda_fp16.h>
#include <cstdint>

#define HID    128
#define KPAD   2048            // padded K (relations)
#define KB     64              // K per chunk (64 halves = 128 B rows)
#define NCH    (KPAD / KB)     // 32 chunks
#define MTILE  128
#define NBKT   4096            // (16384/128) tiles x 32 chunks
#define BCAP   2048            // payload capacity per bucket (mean ~1000)
#define TILE_BYTES 16384       // 128 x 64 fp16
#define SMEM_TOT   (4 * TILE_BYTES)   // A0,A1,B0,B1 = 64 KB

// ---- static device scratch ----
__device__ __half   g_Bt [HID * KPAD];       // Bt[n][k] transformed table (512 KB)
__device__ float    g_Wt [HID * HID];        // W transposed
__device__ float    g_T32[KPAD * HID];       // fp32 T[r][o] (1 MB)
__device__ unsigned g_pay[NBKT * BCAP];      // packed (half<<16 | row<<6 | rel) 32 MB
__device__ int      g_cur[NBKT];             // bucket cursors

// ===========================================================================
// helpers
// ===========================================================================
__device__ __forceinline__ uint32_t smem_u32(const void* p) {
    uint32_t a;
    asm("{ .reg .u64 t; cvta.to.shared.u64 t, %1; cvt.u32.u64 %0, t; }"
        : "=r"(a) : "l"(p));
    return a;
}
__device__ __forceinline__ void cp_async16(uint32_t dst, const void* src) {
    asm volatile("cp.async.cg.shared.global [%0], [%1], 16;"
                 :: "r"(dst), "l"(src) : "memory");
}
__device__ __forceinline__ void ldsm_x4(uint32_t& r0, uint32_t& r1,
                                        uint32_t& r2, uint32_t& r3, uint32_t a) {
    asm volatile("ldmatrix.sync.aligned.m8n8.x4.shared.b16 {%0,%1,%2,%3}, [%4];"
                 : "=r"(r0), "=r"(r1), "=r"(r2), "=r"(r3) : "r"(a));
}
__device__ __forceinline__ void mma16816(float* c, const uint32_t* a,
                                         uint32_t b0, uint32_t b1) {
    asm volatile(
        "mma.sync.aligned.m16n8k16.row.col.f32.f16.f16.f32 "
        "{%0,%1,%2,%3}, {%4,%5,%6,%7}, {%8,%9}, {%0,%1,%2,%3};"
        : "+f"(c[0]), "+f"(c[1]), "+f"(c[2]), "+f"(c[3])
        : "r"(a[0]), "r"(a[1]), "r"(a[2]), "r"(a[3]), "r"(b0), "r"(b1));
}
#define SWZ_OFF(row, chunk) (((row) * 128) + ((((chunk) ^ ((row) & 7))) << 4))

// ===========================================================================
// W transpose: Wt[i][o] = W[o][i]
// ===========================================================================
__global__ void __launch_bounds__(256) wtrans_kernel(const float* __restrict__ W)
{
    __shared__ float t[32][33];
    const int tx = threadIdx.x & 31, ty = threadIdx.x >> 5;
    const int bi = (blockIdx.x & 3) * 32;
    const int bo = (blockIdx.x >> 2) * 32;
#pragma unroll
    for (int j = 0; j < 4; j++)
        t[ty + j * 8][tx] = W[(bo + ty + j * 8) * HID + bi + tx];
    __syncthreads();
#pragma unroll
    for (int j = 0; j < 4; j++)
        g_Wt[(bi + ty + j * 8) * HID + bo + tx] = t[tx][ty + j * 8];
}

// ===========================================================================
// Transform: T32[r][o] = b[o] + sum_i x[r][i] * Wt[i][o].  Warp per relation.
// ===========================================================================
__global__ void __launch_bounds__(256) transform_kernel(
    const float* __restrict__ rel_features,
    const float* __restrict__ b,
    int R)
{
    __shared__ float xs[8][HID];
    const int wid  = threadIdx.x >> 5;
    const int lane = threadIdx.x & 31;
    const int r    = blockIdx.x * 8 + wid;
    if (r >= R) return;

    ((float4*)xs[wid])[lane] = ((const float4*)(rel_features + (size_t)r * HID))[lane];
    __syncwarp();

    float4 acc = ((const float4*)b)[lane];
    const float4* __restrict__ Wt4 = (const float4*)g_Wt;
#pragma unroll 8
    for (int i = 0; i < HID; i++) {
        float  xi = xs[wid][i];
        float4 w  = Wt4[i * 32 + lane];
        acc.x = fmaf(xi, w.x, acc.x);
        acc.y = fmaf(xi, w.y, acc.y);
        acc.z = fmaf(xi, w.z, acc.z);
        acc.w = fmaf(xi, w.w, acc.w);
    }
    ((float4*)(g_T32 + (size_t)r * HID))[lane] = acc;
}

// ===========================================================================
// T transpose + f32->f16: Bt[o][r] = (half)T32[r][o]; zero-fills r >= R.
// ===========================================================================
__global__ void __launch_bounds__(256) ttrans_kernel(int R)
{
    __shared__ float t[32][33];
    const int tx = threadIdx.x & 31, ty = threadIdx.x >> 5;
    const int r0 = blockIdx.x * 32;
    const int o0 = blockIdx.y * 32;
#pragma unroll
    for (int j = 0; j < 4; j++) {
        int r = r0 + ty + j * 8;
        t[ty + j * 8][tx] = (r < R) ? g_T32[(size_t)r * HID + o0 + tx] : 0.f;
    }
    __syncthreads();
#pragma unroll
    for (int j = 0; j < 4; j++)
        g_Bt[(size_t)(o0 + ty + j * 8) * KPAD + r0 + tx] =
            __float2half(t[tx][ty + j * 8]);
}

// ===========================================================================
// Payload fill: bucket facts by (entity>>7, rel>>6); packed u32 entries.
// ===========================================================================
__global__ void __launch_bounds__(256) payfill_kernel(
    const int* __restrict__ heads,
    const int* __restrict__ tails,
    const int* __restrict__ rels,
    const float* __restrict__ val,
    int E)
{
    int stride = gridDim.x * blockDim.x;
    for (int f = blockIdx.x * blockDim.x + threadIdx.x; f < E; f += stride) {
        const int r  = rels[f];
        const int t  = tails[f];
        const int h  = heads[f];
        const unsigned hv = (unsigned)__half_as_ushort(__float2half(val[f])) << 16;
        const int cb = r >> 6, rl = r & 63;

        int bt = (t >> 7) * NCH + cb;
        int it = atomicAdd(&g_cur[bt], 1);
        if (it < BCAP) g_pay[bt * BCAP + it] = hv | (unsigned)((t & 127) << 6) | rl;

        int bh = (h >> 7) * NCH + cb;
        int ih = atomicAdd(&g_cur[bh], 1);
        if (ih < BCAP) g_pay[bh * BCAP + ih] = hv | (unsigned)((h & 127) << 6) | rl;
    }
}

// ===========================================================================
// GEMM: out = relu(S @ Bt^T), A tiles built in smem from payload buckets.
// CTA = 128M x 128N, 256 thr / 8 warps, warp tile 32M x 64N, HMMA m16n8k16.
// smem: A0,A1 (scatter targets), B0,B1 (cp.async), 16 KB each.
// ===========================================================================
__global__ void __launch_bounds__(256) gemm_kernel(
    float* __restrict__ out, int num_ent)
{
    extern __shared__ char smem[];
    const uint32_t sb = smem_u32(smem);

    const int tid  = threadIdx.x;
    const int lane = tid & 31;
    const int wid  = tid >> 5;
    const int m0   = blockIdx.x * MTILE;
    const int mo   = (wid >> 1) * 32;
    const int no   = (wid & 1) * 64;

    float acc[2][8][4];
#pragma unroll
    for (int i = 0; i < 2; i++)
#pragma unroll
        for (int j = 0; j < 8; j++)
#pragma unroll
            for (int k = 0; k < 4; k++) acc[i][j][k] = 0.f;

    // A buffers at sb + buf*16K; B buffers at sb + 32K + buf*16K
    auto zeroA = [&](int buf) {
        uint4* p = (uint4*)(smem + buf * TILE_BYTES);
#pragma unroll
        for (int i = 0; i < 4; i++)
            p[tid + i * 256] = make_uint4(0, 0, 0, 0);
    };
    auto scatterA = [&](int s, int buf) {
        const int bkt = blockIdx.x * NCH + s;
        int n = g_cur[bkt];
        if (n > BCAP) n = BCAP;
        const unsigned* __restrict__ pp = g_pay + (size_t)bkt * BCAP;
        char* base = smem + buf * TILE_BYTES;
        for (int i = tid; i < n; i += 256) {
            unsigned p  = pp[i];
            int row = (p >> 6) & 127;
            int rl  = p & 63;
            int off = row * 128 + ((((rl >> 3) ^ (row & 7)) & 7) << 4) + (rl & 7) * 2;
            atomicAdd((__half*)(base + off), __ushort_as_half((unsigned short)(p >> 16)));
        }
    };
    auto loadB = [&](int s, int buf) {
        const int k0 = s * KB;
        const uint32_t bB = sb + 2 * TILE_BYTES + buf * TILE_BYTES;
#pragma unroll
        for (int i = 0; i < 4; i++) {
            int idx = tid + i * 256;        // 0..1023 16B chunks
            int row = idx >> 3, c = idx & 7;
            cp_async16(bB + SWZ_OFF(row, c),
                       g_Bt + (size_t)row * KPAD + k0 + c * 8);
        }
        asm volatile("cp.async.commit_group;" ::: "memory");
    };

    // prologue: zero both A buffers, start B0, scatter stage 0 into A0
    zeroA(0);
    zeroA(1);
    loadB(0, 0);
    __syncthreads();
    scatterA(0, 0);

    for (int s = 0; s < NCH; s++) {
        asm volatile("cp.async.wait_group 0;" ::: "memory");
        __syncthreads();   // B[s&1] visible; scatter for s complete

        if (s + 1 < NCH) {
            loadB(s + 1, (s + 1) & 1);     // B_next buf free (consumed in s-1)
            zeroA((s + 1) & 1);            // A_next buf free (consumed in s-1)
            __syncthreads();               // zeros visible before scatter
            scatterA(s + 1, (s + 1) & 1);
        }

        const uint32_t bA = sb + (s & 1) * TILE_BYTES;
        const uint32_t bB = sb + 2 * TILE_BYTES + (s & 1) * TILE_BYTES;

#pragma unroll
        for (int ks = 0; ks < 4; ks++) {
            uint32_t a[2][4];
#pragma unroll
            for (int im = 0; im < 2; im++) {
                int row   = mo + im * 16 + (lane & 15);
                int chunk = ks * 2 + (lane >> 4);
                ldsm_x4(a[im][0], a[im][1], a[im][2], a[im][3],
                        bA + SWZ_OFF(row, chunk));
            }
            uint32_t br[4][4];
#pragma unroll
            for (int jn = 0; jn < 4; jn++) {
                int nrow  = no + jn * 16 + (lane & 7) + (((lane >> 3) & 1) << 3);
                int chunk = ks * 2 + (lane >> 4);
                ldsm_x4(br[jn][0], br[jn][1], br[jn][2], br[jn][3],
                        bB + SWZ_OFF(nrow, chunk));
            }
#pragma unroll
            for (int im = 0; im < 2; im++)
#pragma unroll
                for (int jn = 0; jn < 4; jn++) {
                    mma16816(acc[im][jn * 2 + 0], a[im], br[jn][0], br[jn][2]);
                    mma16816(acc[im][jn * 2 + 1], a[im], br[jn][1], br[jn][3]);
                }
        }
    }

    // epilogue: ReLU + store
#pragma unroll
    for (int im = 0; im < 2; im++) {
        int row0 = m0 + mo + im * 16 + (lane >> 2);
#pragma unroll
        for (int j = 0; j < 8; j++) {
            int col = no + j * 8 + (lane & 3) * 2;
            float* c = acc[im][j];
            if (row0 < num_ent) {
                float2 v = make_float2(fmaxf(c[0], 0.f), fmaxf(c[1], 0.f));
                *(float2*)(out + (size_t)row0 * HID + col) = v;
            }
            if (row0 + 8 < num_ent) {
                float2 v = make_float2(fmaxf(c[2], 0.f), fmaxf(c[3], 0.f));
                *(float2*)(out + (size_t)(row0 + 8) * HID + col) = v;
            }
        }
    }
}

// ===========================================================================
// Inputs: 0 local_entity(unused) 1 heads 2 tails 3 rels 4 val
//         5 rel_features[R,128] 6 W[128,128] 7 b[128]  -> out f32 [num_ent,128]
// ===========================================================================
extern "C" void kernel_launch(void* const* d_in, const int* in_sizes, int n_in,
                              void* d_out, int out_size)
{
    const int*   heads = (const int*)  d_in[1];
    const int*   tails = (const int*)  d_in[2];
    const int*   rels  = (const int*)  d_in[3];
    const float* val   = (const float*)d_in[4];
    const float* rel_f = (const float*)d_in[5];
    const float* W     = (const float*)d_in[6];
    const float* b     = (const float*)d_in[7];
    float*       out   = (float*)d_out;

    const int E       = in_sizes[1];
    const int R       = in_sizes[5] / HID;
    const int num_ent = out_size / HID;
    const int mtiles  = (num_ent + MTILE - 1) / MTILE;

    void* curPtr = nullptr;
    cudaGetSymbolAddress(&curPtr, g_cur);
    cudaMemsetAsync(curPtr, 0, NBKT * sizeof(int));

    cudaFuncSetAttribute(gemm_kernel,
                         cudaFuncAttributeMaxDynamicSharedMemorySize, SMEM_TOT);

    wtrans_kernel<<<16, 256>>>(W);
    transform_kernel<<<(R + 7) / 8, 256>>>(rel_f, b, R);
    {
        dim3 g(KPAD / 32, HID / 32);
        ttrans_kernel<<<g, 256>>>(R);
    }
    payfill_kernel<<<2048, 256>>>(heads, tails, rels, val, E);
    gemm_kernel<<<mtiles, 256, SMEM_TOT>>>(out, num_ent);
}

// round 8
// speedup vs baseline: 2.2493x; 2.2493x over previous
#include <cuda_runtime.h>
#include <cuda_fp16.h>
#include <cstdint>

#define HID    128
#define KPAD   2048            // padded K (relations)
#define MAXE   16384           // padded entity rows
#define KB     64              // K per pipeline chunk (64 halves = 128 B rows)
#define NCH    (KPAD / KB)     // 32 chunks
#define STG_BYTES 32768        // A(16KB)+B(16KB) per stage
#define NSTAGES   3
#define SMEM_TOT  (NSTAGES * STG_BYTES)

// ---- static device scratch ----
__device__ __half g_S  [MAXE * KPAD];  // dense incidence-value matrix (64 MB)
__device__ __half g_Bt [HID  * KPAD];  // Bt[n][k]: transformed table, transposed (512 KB)
__device__ float  g_Wt [HID * HID];    // W transposed: Wt[i][o] = W[o][i]
__device__ float  g_T32[KPAD * HID];   // fp32 T[r][o] before transpose (1 MB)

// ===========================================================================
// helpers
// ===========================================================================
__device__ __forceinline__ uint32_t smem_u32(const void* p) {
    uint32_t a;
    asm("{ .reg .u64 t; cvta.to.shared.u64 t, %1; cvt.u32.u64 %0, t; }"
        : "=r"(a) : "l"(p));
    return a;
}
__device__ __forceinline__ void cp_async16(uint32_t dst, const void* src) {
    asm volatile("cp.async.cg.shared.global [%0], [%1], 16;"
                 :: "r"(dst), "l"(src) : "memory");
}
__device__ __forceinline__ void ldsm_x4(uint32_t& r0, uint32_t& r1,
                                        uint32_t& r2, uint32_t& r3, uint32_t a) {
    asm volatile("ldmatrix.sync.aligned.m8n8.x4.shared.b16 {%0,%1,%2,%3}, [%4];"
                 : "=r"(r0), "=r"(r1), "=r"(r2), "=r"(r3) : "r"(a));
}
__device__ __forceinline__ void mma16816(float* c, const uint32_t* a,
                                         uint32_t b0, uint32_t b1) {
    asm volatile(
        "mma.sync.aligned.m16n8k16.row.col.f32.f16.f16.f32 "
        "{%0,%1,%2,%3}, {%4,%5,%6,%7}, {%8,%9}, {%0,%1,%2,%3};"
        : "+f"(c[0]), "+f"(c[1]), "+f"(c[2]), "+f"(c[3])
        : "r"(a[0]), "r"(a[1]), "r"(a[2]), "r"(a[3]), "r"(b0), "r"(b1));
}
#define SWZ_OFF(row, chunk) (((row) * 128) + ((((chunk) ^ ((row) & 7))) << 4))

// ===========================================================================
// W transpose: Wt[i][o] = W[o][i]
// ===========================================================================
__global__ void __launch_bounds__(256) wtrans_kernel(const float* __restrict__ W)
{
    __shared__ float t[32][33];
    const int tx = threadIdx.x & 31, ty = threadIdx.x >> 5;
    const int bi = (blockIdx.x & 3) * 32;
    const int bo = (blockIdx.x >> 2) * 32;
#pragma unroll
    for (int j = 0; j < 4; j++)
        t[ty + j * 8][tx] = W[(bo + ty + j * 8) * HID + bi + tx];
    __syncthreads();
#pragma unroll
    for (int j = 0; j < 4; j++)
        g_Wt[(bi + ty + j * 8) * HID + bo + tx] = t[tx][ty + j * 8];
}

// ===========================================================================
// Transform: T32[r][o] = b[o] + sum_i x[r][i] * Wt[i][o].  Warp per relation.
// ===========================================================================
__global__ void __launch_bounds__(256) transform_kernel(
    const float* __restrict__ rel_features,
    const float* __restrict__ b,
    int R)
{
    __shared__ float xs[8][HID];
    const int wid  = threadIdx.x >> 5;
    const int lane = threadIdx.x & 31;
    const int r    = blockIdx.x * 8 + wid;
    if (r >= R) return;

    ((float4*)xs[wid])[lane] = ((const float4*)(rel_features + (size_t)r * HID))[lane];
    __syncwarp();

    float4 acc = ((const float4*)b)[lane];
    const float4* __restrict__ Wt4 = (const float4*)g_Wt;
#pragma unroll 8
    for (int i = 0; i < HID; i++) {
        float  xi = xs[wid][i];
        float4 w  = Wt4[i * 32 + lane];
        acc.x = fmaf(xi, w.x, acc.x);
        acc.y = fmaf(xi, w.y, acc.y);
        acc.z = fmaf(xi, w.z, acc.z);
        acc.w = fmaf(xi, w.w, acc.w);
    }
    ((float4*)(g_T32 + (size_t)r * HID))[lane] = acc;
}

// ===========================================================================
// T transpose + f32->f16: Bt[o][r] = (half)T32[r][o]; zero-fills r >= R.
// ===========================================================================
__global__ void __launch_bounds__(256) ttrans_kernel(int R)
{
    __shared__ float t[32][33];
    const int tx = threadIdx.x & 31, ty = threadIdx.x >> 5;
    const int r0 = blockIdx.x * 32;
    const int o0 = blockIdx.y * 32;
#pragma unroll
    for (int j = 0; j < 4; j++) {
        int r = r0 + ty + j * 8;
        t[ty + j * 8][tx] = (r < R) ? g_T32[(size_t)r * HID + o0 + tx] : 0.f;
    }
    __syncthreads();
#pragma unroll
    for (int j = 0; j < 4; j++)
        g_Bt[(size_t)(o0 + ty + j * 8) * KPAD + r0 + tx] =
            __float2half(t[tx][ty + j * 8]);
}

// ===========================================================================
// Fill dense S with NATIVE packed f16x2 L2 reductions.
// Each fact updates one fp16 lane of a 4B-aligned __half2:
//   S[e][r & ~1] += (r odd) ? (0, v) : (v, 0)
// Avoids the slow sub-word (2B) RMW path at the LTS.
// ===========================================================================
__global__ void __launch_bounds__(256) fill_kernel(
    const int* __restrict__ heads,
    const int* __restrict__ tails,
    const int* __restrict__ rels,
    const float* __restrict__ val,
    int E)
{
    const __half hz = __float2half(0.0f);
    int stride = gridDim.x * blockDim.x;
    for (int f = blockIdx.x * blockDim.x + threadIdx.x; f < E; f += stride) {
        const int    r  = rels[f];
        const __half hv = __float2half(val[f]);
        const __half2 v2 = (r & 1) ? __halves2half2(hz, hv)
                                   : __halves2half2(hv, hz);
        const int rp = r & ~1;
        atomicAdd((__half2*)(g_S + (size_t)tails[f] * KPAD + rp), v2);
        atomicAdd((__half2*)(g_S + (size_t)heads[f] * KPAD + rp), v2);
    }
}

// ===========================================================================
// GEMM: out = relu(S @ Bt^T).  CTA = 128M x 128N tile, 256 thr / 8 warps,
// warp tile 32M x 64N, m16n8k16 HMMA, 3-stage cp.async pipeline.
// ===========================================================================
__global__ void __launch_bounds__(256) gemm_kernel(
    float* __restrict__ out, int num_ent)
{
    extern __shared__ char smem[];
    const uint32_t sb = smem_u32(smem);

    const int tid  = threadIdx.x;
    const int lane = tid & 31;
    const int wid  = tid >> 5;
    const int m0   = blockIdx.x * 128;
    const int mo   = (wid >> 1) * 32;
    const int no   = (wid & 1) * 64;

    float acc[2][8][4];
#pragma unroll
    for (int i = 0; i < 2; i++)
#pragma unroll
        for (int j = 0; j < 8; j++)
#pragma unroll
            for (int k = 0; k < 4; k++) acc[i][j][k] = 0.f;

    auto load_stage = [&](int s, int buf) {
        const int k0 = s * KB;
        const uint32_t bA = sb + buf * STG_BYTES;
        const uint32_t bB = bA + 16384;
#pragma unroll
        for (int i = 0; i < 4; i++) {
            int idx = tid + i * 256;          // 0..1023
            int row = idx >> 3, c = idx & 7;
            cp_async16(bA + SWZ_OFF(row, c),
                       g_S + (size_t)(m0 + row) * KPAD + k0 + c * 8);
            cp_async16(bB + SWZ_OFF(row, c),
                       g_Bt + (size_t)row * KPAD + k0 + c * 8);
        }
        asm volatile("cp.async.commit_group;" ::: "memory");
    };

    load_stage(0, 0);
    load_stage(1, 1);

    for (int s = 0; s < NCH; s++) {
        if (s + 2 < NCH) {
            load_stage(s + 2, (s + 2) % NSTAGES);
            asm volatile("cp.async.wait_group 2;" ::: "memory");
        } else if (s + 1 < NCH) {
            asm volatile("cp.async.wait_group 1;" ::: "memory");
        } else {
            asm volatile("cp.async.wait_group 0;" ::: "memory");
        }
        __syncthreads();

        const uint32_t bA = sb + (s % NSTAGES) * STG_BYTES;
        const uint32_t bB = bA + 16384;

#pragma unroll
        for (int ks = 0; ks < 4; ks++) {
            uint32_t a[2][4];
#pragma unroll
            for (int im = 0; im < 2; im++) {
                int row   = mo + im * 16 + (lane & 15);
                int chunk = ks * 2 + (lane >> 4);
                ldsm_x4(a[im][0], a[im][1], a[im][2], a[im][3],
                        bA + SWZ_OFF(row, chunk));
            }
            uint32_t br[4][4];
#pragma unroll
            for (int jn = 0; jn < 4; jn++) {
                int nrow  = no + jn * 16 + (lane & 7) + (((lane >> 3) & 1) << 3);
                int chunk = ks * 2 + (lane >> 4);
                ldsm_x4(br[jn][0], br[jn][1], br[jn][2], br[jn][3],
                        bB + SWZ_OFF(nrow, chunk));
            }
#pragma unroll
            for (int im = 0; im < 2; im++)
#pragma unroll
                for (int jn = 0; jn < 4; jn++) {
                    mma16816(acc[im][jn * 2 + 0], a[im], br[jn][0], br[jn][2]);
                    mma16816(acc[im][jn * 2 + 1], a[im], br[jn][1], br[jn][3]);
                }
        }
        __syncthreads();
    }

    // epilogue: ReLU + store
#pragma unroll
    for (int im = 0; im < 2; im++) {
        int row0 = m0 + mo + im * 16 + (lane >> 2);
#pragma unroll
        for (int j = 0; j < 8; j++) {
            int col = no + j * 8 + (lane & 3) * 2;
            float* c = acc[im][j];
            if (row0 < num_ent) {
                float2 v = make_float2(fmaxf(c[0], 0.f), fmaxf(c[1], 0.f));
                *(float2*)(out + (size_t)row0 * HID + col) = v;
            }
            if (row0 + 8 < num_ent) {
                float2 v = make_float2(fmaxf(c[2], 0.f), fmaxf(c[3], 0.f));
                *(float2*)(out + (size_t)(row0 + 8) * HID + col) = v;
            }
        }
    }
}

// ===========================================================================
// Inputs: 0 local_entity(unused) 1 heads 2 tails 3 rels 4 val
//         5 rel_features[R,128] 6 W[128,128] 7 b[128]  -> out f32 [num_ent,128]
// ===========================================================================
extern "C" void kernel_launch(void* const* d_in, const int* in_sizes, int n_in,
                              void* d_out, int out_size)
{
    const int*   heads = (const int*)  d_in[1];
    const int*   tails = (const int*)  d_in[2];
    const int*   rels  = (const int*)  d_in[3];
    const float* val   = (const float*)d_in[4];
    const float* rel_f = (const float*)d_in[5];
    const float* W     = (const float*)d_in[6];
    const float* b     = (const float*)d_in[7];
    float*       out   = (float*)d_out;

    const int E       = in_sizes[1];
    const int R       = in_sizes[5] / HID;
    const int num_ent = out_size / HID;
    const int mtiles  = (num_ent + 127) / 128;

    void* sPtr = nullptr;
    cudaGetSymbolAddress(&sPtr, g_S);
    cudaMemsetAsync(sPtr, 0, sizeof(__half) * (size_t)MAXE * KPAD);

    cudaFuncSetAttribute(gemm_kernel,
                         cudaFuncAttributeMaxDynamicSharedMemorySize, SMEM_TOT);

    wtrans_kernel<<<16, 256>>>(W);
    transform_kernel<<<(R + 7) / 8, 256>>>(rel_f, b, R);
    {
        dim3 g(KPAD / 32, HID / 32);
        ttrans_kernel<<<g, 256>>>(R);
    }
    fill_kernel<<<2048, 256>>>(heads, tails, rels, val, E);
    gemm_kernel<<<mtiles, 256, SMEM_TOT>>>(out, num_ent);
}

// round 9
// speedup vs baseline: 2.2569x; 1.0034x over previous
#include <cuda_runtime.h>
#include <cuda_fp16.h>
#include <cstdint>

#define HID    128
#define KPAD   2048            // padded K (relations)
#define MAXE   16384           // padded entity rows
#define KB     64              // K per pipeline chunk (64 halves = 128 B rows)
#define NCH    (KPAD / KB)     // 32 chunks
#define STG_BYTES 32768        // A(16KB)+B(16KB) per stage
#define NSTAGES   3
#define SMEM_TOT  (NSTAGES * STG_BYTES)

// ---- static device scratch ----
__device__ __half g_S  [MAXE * KPAD];  // dense incidence-value matrix (64 MB)
__device__ __half g_Bt [HID  * KPAD];  // Bt[n][k]: transformed table, transposed (512 KB)
__device__ float  g_Wt [HID * HID];    // W transposed: Wt[i][o] = W[o][i]
__device__ float  g_T32[KPAD * HID];   // fp32 T[r][o] before transpose (1 MB)

// ===========================================================================
// helpers
// ===========================================================================
__device__ __forceinline__ uint32_t smem_u32(const void* p) {
    uint32_t a;
    asm("{ .reg .u64 t; cvta.to.shared.u64 t, %1; cvt.u32.u64 %0, t; }"
        : "=r"(a) : "l"(p));
    return a;
}
__device__ __forceinline__ void cp_async16(uint32_t dst, const void* src) {
    asm volatile("cp.async.cg.shared.global [%0], [%1], 16;"
                 :: "r"(dst), "l"(src) : "memory");
}
__device__ __forceinline__ void ldsm_x4(uint32_t& r0, uint32_t& r1,
                                        uint32_t& r2, uint32_t& r3, uint32_t a) {
    asm volatile("ldmatrix.sync.aligned.m8n8.x4.shared.b16 {%0,%1,%2,%3}, [%4];"
                 : "=r"(r0), "=r"(r1), "=r"(r2), "=r"(r3) : "r"(a));
}
__device__ __forceinline__ void mma16816(float* c, const uint32_t* a,
                                         uint32_t b0, uint32_t b1) {
    asm volatile(
        "mma.sync.aligned.m16n8k16.row.col.f32.f16.f16.f32 "
        "{%0,%1,%2,%3}, {%4,%5,%6,%7}, {%8,%9}, {%0,%1,%2,%3};"
        : "+f"(c[0]), "+f"(c[1]), "+f"(c[2]), "+f"(c[3])
        : "r"(a[0]), "r"(a[1]), "r"(a[2]), "r"(a[3]), "r"(b0), "r"(b1));
}
#define SWZ_OFF(row, chunk) (((row) * 128) + ((((chunk) ^ ((row) & 7))) << 4))

// ===========================================================================
// W transpose: Wt[i][o] = W[o][i]
// ===========================================================================
__global__ void __launch_bounds__(256) wtrans_kernel(const float* __restrict__ W)
{
    __shared__ float t[32][33];
    const int tx = threadIdx.x & 31, ty = threadIdx.x >> 5;
    const int bi = (blockIdx.x & 3) * 32;
    const int bo = (blockIdx.x >> 2) * 32;
#pragma unroll
    for (int j = 0; j < 4; j++)
        t[ty + j * 8][tx] = W[(bo + ty + j * 8) * HID + bi + tx];
    __syncthreads();
#pragma unroll
    for (int j = 0; j < 4; j++)
        g_Wt[(bi + ty + j * 8) * HID + bo + tx] = t[tx][ty + j * 8];
}

// ===========================================================================
// Transform: T32[r][o] = b[o] + sum_i x[r][i] * Wt[i][o].  Warp per relation.
// ===========================================================================
__global__ void __launch_bounds__(256) transform_kernel(
    const float* __restrict__ rel_features,
    const float* __restrict__ b,
    int R)
{
    __shared__ float xs[8][HID];
    const int wid  = threadIdx.x >> 5;
    const int lane = threadIdx.x & 31;
    const int r    = blockIdx.x * 8 + wid;
    if (r >= R) return;

    ((float4*)xs[wid])[lane] = ((const float4*)(rel_features + (size_t)r * HID))[lane];
    __syncwarp();

    float4 acc = ((const float4*)b)[lane];
    const float4* __restrict__ Wt4 = (const float4*)g_Wt;
#pragma unroll 8
    for (int i = 0; i < HID; i++) {
        float  xi = xs[wid][i];
        float4 w  = Wt4[i * 32 + lane];
        acc.x = fmaf(xi, w.x, acc.x);
        acc.y = fmaf(xi, w.y, acc.y);
        acc.z = fmaf(xi, w.z, acc.z);
        acc.w = fmaf(xi, w.w, acc.w);
    }
    ((float4*)(g_T32 + (size_t)r * HID))[lane] = acc;
}

// ===========================================================================
// T transpose + f32->f16: Bt[o][r] = (half)T32[r][o]; zero-fills r >= R.
// ===========================================================================
__global__ void __launch_bounds__(256) ttrans_kernel(int R)
{
    __shared__ float t[32][33];
    const int tx = threadIdx.x & 31, ty = threadIdx.x >> 5;
    const int r0 = blockIdx.x * 32;
    const int o0 = blockIdx.y * 32;
#pragma unroll
    for (int j = 0; j < 4; j++) {
        int r = r0 + ty + j * 8;
        t[ty + j * 8][tx] = (r < R) ? g_T32[(size_t)r * HID + o0 + tx] : 0.f;
    }
    __syncthreads();
#pragma unroll
    for (int j = 0; j < 4; j++)
        g_Bt[(size_t)(o0 + ty + j * 8) * KPAD + r0 + tx] =
            __float2half(t[tx][ty + j * 8]);
}

// ===========================================================================
// Fill dense S with NATIVE packed f16x2 L2 reductions.
// 4 facts per thread via int4/float4 STREAMING loads (__ldcs: evict-first,
// so the single-use index arrays don't evict S from L2).
//   S[e][r & ~1] += (r odd) ? (0, v) : (v, 0)
// ===========================================================================
__device__ __forceinline__ void fact_red(int h, int t, int r, float v)
{
    unsigned hv = (unsigned)__half_as_ushort(__float2half(v));
    unsigned pk = (r & 1) ? (hv << 16) : hv;
    const __half2 v2 = *reinterpret_cast<const __half2*>(&pk);
    const int rp = r & ~1;
    atomicAdd((__half2*)(g_S + (size_t)t * KPAD + rp), v2);
    atomicAdd((__half2*)(g_S + (size_t)h * KPAD + rp), v2);
}

__global__ void __launch_bounds__(256) fill_kernel(
    const int* __restrict__ heads,
    const int* __restrict__ tails,
    const int* __restrict__ rels,
    const float* __restrict__ val,
    int E)
{
    const int nq = E >> 2;
    const int i  = blockIdx.x * blockDim.x + threadIdx.x;
    if (i < nq) {
        const int4   h = __ldcs((const int4*)heads + i);
        const int4   t = __ldcs((const int4*)tails + i);
        const int4   r = __ldcs((const int4*)rels  + i);
        const float4 v = __ldcs((const float4*)val + i);
        fact_red(h.x, t.x, r.x, v.x);
        fact_red(h.y, t.y, r.y, v.y);
        fact_red(h.z, t.z, r.z, v.z);
        fact_red(h.w, t.w, r.w, v.w);
    } else if (i == nq) {
        // scalar tail for E % 4 != 0
        for (int f = nq * 4; f < E; f++)
            fact_red(__ldcs(heads + f), __ldcs(tails + f),
                     __ldcs(rels + f), __ldcs(val + f));
    }
}

// ===========================================================================
// GEMM: out = relu(S @ Bt^T).  CTA = 128M x 128N tile, 256 thr / 8 warps,
// warp tile 32M x 64N, m16n8k16 HMMA, 3-stage cp.async pipeline.
// ===========================================================================
__global__ void __launch_bounds__(256) gemm_kernel(
    float* __restrict__ out, int num_ent)
{
    extern __shared__ char smem[];
    const uint32_t sb = smem_u32(smem);

    const int tid  = threadIdx.x;
    const int lane = tid & 31;
    const int wid  = tid >> 5;
    const int m0   = blockIdx.x * 128;
    const int mo   = (wid >> 1) * 32;
    const int no   = (wid & 1) * 64;

    float acc[2][8][4];
#pragma unroll
    for (int i = 0; i < 2; i++)
#pragma unroll
        for (int j = 0; j < 8; j++)
#pragma unroll
            for (int k = 0; k < 4; k++) acc[i][j][k] = 0.f;

    auto load_stage = [&](int s, int buf) {
        const int k0 = s * KB;
        const uint32_t bA = sb + buf * STG_BYTES;
        const uint32_t bB = bA + 16384;
#pragma unroll
        for (int i = 0; i < 4; i++) {
            int idx = tid + i * 256;          // 0..1023
            int row = idx >> 3, c = idx & 7;
            cp_async16(bA + SWZ_OFF(row, c),
                       g_S + (size_t)(m0 + row) * KPAD + k0 + c * 8);
            cp_async16(bB + SWZ_OFF(row, c),
                       g_Bt + (size_t)row * KPAD + k0 + c * 8);
        }
        asm volatile("cp.async.commit_group;" ::: "memory");
    };

    load_stage(0, 0);
    load_stage(1, 1);

    for (int s = 0; s < NCH; s++) {
        if (s + 2 < NCH) {
            load_stage(s + 2, (s + 2) % NSTAGES);
            asm volatile("cp.async.wait_group 2;" ::: "memory");
        } else if (s + 1 < NCH) {
            asm volatile("cp.async.wait_group 1;" ::: "memory");
        } else {
            asm volatile("cp.async.wait_group 0;" ::: "memory");
        }
        __syncthreads();

        const uint32_t bA = sb + (s % NSTAGES) * STG_BYTES;
        const uint32_t bB = bA + 16384;

#pragma unroll
        for (int ks = 0; ks < 4; ks++) {
            uint32_t a[2][4];
#pragma unroll
            for (int im = 0; im < 2; im++) {
                int row   = mo + im * 16 + (lane & 15);
                int chunk = ks * 2 + (lane >> 4);
                ldsm_x4(a[im][0], a[im][1], a[im][2], a[im][3],
                        bA + SWZ_OFF(row, chunk));
            }
            uint32_t br[4][4];
#pragma unroll
            for (int jn = 0; jn < 4; jn++) {
                int nrow  = no + jn * 16 + (lane & 7) + (((lane >> 3) & 1) << 3);
                int chunk = ks * 2 + (lane >> 4);
                ldsm_x4(br[jn][0], br[jn][1], br[jn][2], br[jn][3],
                        bB + SWZ_OFF(nrow, chunk));
            }
#pragma unroll
            for (int im = 0; im < 2; im++)
#pragma unroll
                for (int jn = 0; jn < 4; jn++) {
                    mma16816(acc[im][jn * 2 + 0], a[im], br[jn][0], br[jn][2]);
                    mma16816(acc[im][jn * 2 + 1], a[im], br[jn][1], br[jn][3]);
                }
        }
        __syncthreads();
    }

    // epilogue: ReLU + store
#pragma unroll
    for (int im = 0; im < 2; im++) {
        int row0 = m0 + mo + im * 16 + (lane >> 2);
#pragma unroll
        for (int j = 0; j < 8; j++) {
            int col = no + j * 8 + (lane & 3) * 2;
            float* c = acc[im][j];
            if (row0 < num_ent) {
                float2 v = make_float2(fmaxf(c[0], 0.f), fmaxf(c[1], 0.f));
                *(float2*)(out + (size_t)row0 * HID + col) = v;
            }
            if (row0 + 8 < num_ent) {
                float2 v = make_float2(fmaxf(c[2], 0.f), fmaxf(c[3], 0.f));
                *(float2*)(out + (size_t)(row0 + 8) * HID + col) = v;
            }
        }
    }
}

// ===========================================================================
// Inputs: 0 local_entity(unused) 1 heads 2 tails 3 rels 4 val
//         5 rel_features[R,128] 6 W[128,128] 7 b[128]  -> out f32 [num_ent,128]
// ===========================================================================
extern "C" void kernel_launch(void* const* d_in, const int* in_sizes, int n_in,
                              void* d_out, int out_size)
{
    const int*   heads = (const int*)  d_in[1];
    const int*   tails = (const int*)  d_in[2];
    const int*   rels  = (const int*)  d_in[3];
    const float* val   = (const float*)d_in[4];
    const float* rel_f = (const float*)d_in[5];
    const float* W     = (const float*)d_in[6];
    const float* b     = (const float*)d_in[7];
    float*       out   = (float*)d_out;

    const int E       = in_sizes[1];
    const int R       = in_sizes[5] / HID;
    const int num_ent = out_size / HID;
    const int mtiles  = (num_ent + 127) / 128;

    void* sPtr = nullptr;
    cudaGetSymbolAddress(&sPtr, g_S);
    cudaMemsetAsync(sPtr, 0, sizeof(__half) * (size_t)MAXE * KPAD);

    cudaFuncSetAttribute(gemm_kernel,
                         cudaFuncAttributeMaxDynamicSharedMemorySize, SMEM_TOT);

    wtrans_kernel<<<16, 256>>>(W);
    transform_kernel<<<(R + 7) / 8, 256>>>(rel_f, b, R);
    {
        dim3 g(KPAD / 32, HID / 32);
        ttrans_kernel<<<g, 256>>>(R);
    }
    const int nthreads = E / 4 + 1;
    fill_kernel<<<(nthreads + 255) / 256, 256>>>(heads, tails, rels, val, E);
    gemm_kernel<<<mtiles, 256, SMEM_TOT>>>(out, num_ent);
}